// round 4
// baseline (speedup 1.0000x reference)
#include <cuda_runtime.h>
#include <cstdint>

// ---------------------------------------------------------------------------
// GAT layer, algebraically reduced:
//   Sum_{e: src=n} alpha[e,h] == 1{outdeg(n)>0} in fp32
//   => out = (h_in @ W.T + b) * outdeg_mask
//
// R3 lesson: GEMM was L1TEX-wavefront bound, not FMA bound.
//   - W broadcast through LDS costs 4 cyc/op (512B RF writeback).
//   - per-lane-row LDG.128 = 32 lines = 32 wavefronts per warp op.
// Fix: W via warp-uniform LDG (nL=1 -> 1 wf), R=4 rows/thread, mask fused
// into the GEMM epilogue (no third kernel).
// ---------------------------------------------------------------------------

#define MASK_CAP (1 << 20)
__device__ unsigned char       g_mask[MASK_CAP];          // generic fallback
__device__ unsigned int        g_bits[MASK_CAP / 32];     // fast path bitmask
__device__ __align__(16) unsigned long long g_Wt[128 * 16]; // [k][j2] pairs
__device__ __align__(16) unsigned long long g_b2[16];       // bias pairs

__device__ __forceinline__ unsigned long long pack2(float x, float y) {
    unsigned long long r;
    asm("mov.b64 %0, {%1, %2};" : "=l"(r) : "f"(x), "f"(y));
    return r;
}
__device__ __forceinline__ float2 unpack2(unsigned long long v) {
    float2 r;
    asm("mov.b64 {%0, %1}, %2;" : "=f"(r.x), "=f"(r.y) : "l"(v));
    return r;
}
__device__ __forceinline__ void fma2(unsigned long long& acc,
                                     unsigned long long a, unsigned long long b) {
    asm("fma.rn.f32x2 %0, %1, %2, %3;" : "=l"(acc) : "l"(a), "l"(b), "l"(acc));
}
__device__ __forceinline__ unsigned long long mul2(unsigned long long a,
                                                   unsigned long long b) {
    unsigned long long r;
    asm("mul.rn.f32x2 %0, %1, %2;" : "=l"(r) : "l"(a), "l"(b));
    return r;
}
// bytes (0/1) of v -> 4 bits, byte j -> bit j
__device__ __forceinline__ unsigned nib(unsigned v) {
    return (((v & 0x01010101u) * 0x01020408u) >> 24) & 0xFu;
}

// ---------------------------------------------------------------------------
// K1: scatter src -> bitmask (smem byte-map private per CTA, atomicOr merge),
// plus CTA 0 transposes W/b into pair-interleaved global buffers for K2.
// ---------------------------------------------------------------------------
__global__ __launch_bounds__(256) void scatter_prep_kernel(
    const int* __restrict__ src, int E, int n, int mapBytes,
    const float* __restrict__ W, const float* __restrict__ b)
{
    extern __shared__ __align__(16) char dsm[];
    const int tid = threadIdx.x;
    const int g   = gridDim.x;

    // CTA 0: transpose W [32,128] -> g_Wt[k][j2] = (W[2j2][k], W[2j2+1][k])
    if (blockIdx.x == 0) {
        for (int idx = tid; idx < 128 * 16; idx += 256) {
            int k = idx >> 4, j2 = idx & 15;
            g_Wt[idx] = pack2(W[(2 * j2) * 128 + k], W[(2 * j2 + 1) * 128 + k]);
        }
        if (tid < 16) g_b2[tid] = pack2(b[2 * tid], b[2 * tid + 1]);
    }

    // zero private byte map
    {
        int4* m4 = reinterpret_cast<int4*>(dsm);
        const int nm4 = mapBytes >> 4;
        for (int i = tid; i < nm4; i += 256) m4[i] = make_int4(0, 0, 0, 0);
    }
    __syncthreads();

    // scatter this CTA's contiguous edge chunk (plain byte STS)
    {
        const int E4  = E >> 2;
        const int per = (E4 + g - 1) / g;
        const int s4  = blockIdx.x * per;
        const int e4  = min(s4 + per, E4);
        const int4* __restrict__ sp = reinterpret_cast<const int4*>(src);
        for (int i = s4 + tid; i < e4; i += 256) {
            int4 s = sp[i];
            if ((unsigned)s.x < (unsigned)n) dsm[s.x] = 1;
            if ((unsigned)s.y < (unsigned)n) dsm[s.y] = 1;
            if ((unsigned)s.z < (unsigned)n) dsm[s.z] = 1;
            if ((unsigned)s.w < (unsigned)n) dsm[s.w] = 1;
        }
        if (blockIdx.x == g - 1) {
            for (int i = (E4 << 2) + tid; i < E; i += 256) {
                int s = src[i];
                if ((unsigned)s < (unsigned)n) dsm[s] = 1;
            }
        }
    }
    __syncthreads();

    // bit-pack + merge into global bit mask
    {
        const int nWords = (n + 31) >> 5;
        const uint4* mv = reinterpret_cast<const uint4*>(dsm);
        for (int w = tid; w < nWords; w += 256) {
            uint4 a = mv[2 * w + 0];
            uint4 c = mv[2 * w + 1];
            unsigned bits =  nib(a.x)        | (nib(a.y) << 4)
                          | (nib(a.z) << 8)  | (nib(a.w) << 12)
                          | (nib(c.x) << 16) | (nib(c.y) << 20)
                          | (nib(c.z) << 24) | (nib(c.w) << 28);
            if (bits) atomicOr(&g_bits[w], bits);
        }
    }
}

// ---------------------------------------------------------------------------
// K2: GEMM 128->32 with fused mask + mask self-clean.
// 128 threads/CTA, 4 rows/thread (stride-128 blocking): rows t+128i.
// W read via warp-uniform LDG.128 (1 wavefront), FFMA2 packed math.
// ---------------------------------------------------------------------------
__global__ __launch_bounds__(128, 3) void gemm_mask_kernel(
    const float* __restrict__ h_in,   // [n, 128]
    float* __restrict__ out,          // [n, 32]
    int n)
{
    const int t    = threadIdx.x;
    const int warp = t >> 5;
    const int lane = t & 31;
    const int base = blockIdx.x * 512;

    int  r[4];
    bool v[4];
    #pragma unroll
    for (int i = 0; i < 4; ++i) { r[i] = base + t + 128 * i; v[i] = r[i] < n; }

    unsigned long long acc[4][16];
    #pragma unroll
    for (int j2 = 0; j2 < 16; ++j2) {
        unsigned long long bb = g_b2[j2];        // uniform LDG
        acc[0][j2] = bb; acc[1][j2] = bb; acc[2][j2] = bb; acc[3][j2] = bb;
    }

    const float4* __restrict__ p[4];
    #pragma unroll
    for (int i = 0; i < 4; ++i)
        p[i] = reinterpret_cast<const float4*>(h_in + (size_t)(v[i] ? r[i] : 0) * 128);

    const ulonglong2* __restrict__ Wt = reinterpret_cast<const ulonglong2*>(g_Wt);

    #pragma unroll 4
    for (int k4 = 0; k4 < 32; ++k4) {
        float4 a0 = p[0][k4];
        float4 a1 = p[1][k4];
        float4 a2 = p[2][k4];
        float4 a3 = p[3][k4];
        float e0[4] = {a0.x, a0.y, a0.z, a0.w};
        float e1[4] = {a1.x, a1.y, a1.z, a1.w};
        float e2[4] = {a2.x, a2.y, a2.z, a2.w};
        float e3[4] = {a3.x, a3.y, a3.z, a3.w};
        #pragma unroll
        for (int u = 0; u < 4; ++u) {
            const int k = 4 * k4 + u;
            unsigned long long x0 = pack2(e0[u], e0[u]);
            unsigned long long x1 = pack2(e1[u], e1[u]);
            unsigned long long x2 = pack2(e2[u], e2[u]);
            unsigned long long x3 = pack2(e3[u], e3[u]);
            #pragma unroll
            for (int j4 = 0; j4 < 8; ++j4) {
                ulonglong2 w = Wt[k * 8 + j4];   // warp-uniform LDG.128, 1 wf
                fma2(acc[0][2 * j4 + 0], x0, w.x);
                fma2(acc[0][2 * j4 + 1], x0, w.y);
                fma2(acc[1][2 * j4 + 0], x1, w.x);
                fma2(acc[1][2 * j4 + 1], x1, w.y);
                fma2(acc[2][2 * j4 + 0], x2, w.x);
                fma2(acc[2][2 * j4 + 1], x2, w.y);
                fma2(acc[3][2 * j4 + 0], x3, w.x);
                fma2(acc[3][2 * j4 + 1], x3, w.y);
            }
        }
    }

    // ---- fused mask: word per i-group is warp-uniform; self-clean after ----
    unsigned wbits[4];
    int widx[4];
    #pragma unroll
    for (int i = 0; i < 4; ++i) {
        widx[i]  = (base + (warp << 5) + (i << 7)) >> 5;   // uniform per warp
        wbits[i] = g_bits[widx[i]];
    }
    __syncwarp();
    if (lane == 0) {
        #pragma unroll
        for (int i = 0; i < 4; ++i) g_bits[widx[i]] = 0;   // reset for next replay
    }

    #pragma unroll
    for (int i = 0; i < 4; ++i) {
        if (!v[i]) continue;
        float mf = ((wbits[i] >> lane) & 1u) ? 1.0f : 0.0f;
        unsigned long long m2 = pack2(mf, mf);
        float4* o = reinterpret_cast<float4*>(out + (size_t)r[i] * 32);
        #pragma unroll
        for (int j4 = 0; j4 < 8; ++j4) {
            float2 v0 = unpack2(mul2(acc[i][2 * j4 + 0], m2));
            float2 v1 = unpack2(mul2(acc[i][2 * j4 + 1], m2));
            o[j4] = make_float4(v0.x, v0.y, v1.x, v1.y);
        }
    }
}

// ---------------------------------------------------------------------------
// Generic fallbacks (any dims) — correctness insurance only.
// ---------------------------------------------------------------------------
__global__ void generic_scatter_kernel(const int* __restrict__ src, int E) {
    int i = blockIdx.x * blockDim.x + threadIdx.x;
    int stride = gridDim.x * blockDim.x;
    for (int e = i; e < E; e += stride) g_mask[src[e]] = 1;
}
__global__ void generic_gemm_kernel(
    const float* __restrict__ h_in, const float* __restrict__ W,
    const float* __restrict__ b, float* __restrict__ out,
    int n, int f_in, int hf)
{
    long long idx = (long long)blockIdx.x * blockDim.x + threadIdx.x;
    if (idx >= (long long)n * hf) return;
    int node = (int)(idx / hf);
    int j    = (int)(idx % hf);
    const float* hr = h_in + (size_t)node * f_in;
    const float* wr = W + (size_t)j * f_in;
    float acc = b[j];
    for (int k = 0; k < f_in; ++k) acc += hr[k] * wr[k];
    out[idx] = acc;
}
__global__ void generic_maskfix_kernel(float* __restrict__ out, int n, int hf) {
    int i = blockIdx.x * blockDim.x + threadIdx.x;
    if (i >= n) return;
    unsigned char m = g_mask[i];
    g_mask[i] = 0;
    if (!m) {
        float* o = out + (size_t)i * hf;
        for (int j = 0; j < hf; ++j) o[j] = 0.0f;
    }
}

extern "C" void kernel_launch(void* const* d_in, const int* in_sizes, int n_in,
                              void* d_out, int out_size) {
    const float* h_in = (const float*)d_in[0];
    const float* W    = (const float*)d_in[1];
    const float* b    = (const float*)d_in[2];
    // d_in[3]=a_src, d_in[4]=a_tgt: provably unused after reduction
    const int* edge_index = (const int*)d_in[5];

    int HF   = in_sizes[2];               // H * F_OUT
    int F_IN = in_sizes[1] / HF;
    int n    = in_sizes[0] / F_IN;
    int E    = in_sizes[5] / 2;
    const int* src = edge_index;          // row 0 of [2, E]

    float* out = (float*)d_out;

    if (F_IN == 128 && HF == 32 && n <= 102400) {
        int mapBytes = (n + 127) & ~127;

        static int inited = 0;
        if (!inited) {
            cudaFuncSetAttribute(scatter_prep_kernel,
                                 cudaFuncAttributeMaxDynamicSharedMemorySize,
                                 104000);
            inited = 1;
        }

        scatter_prep_kernel<<<296, 256, mapBytes>>>(src, E, n, mapBytes, W, b);
        gemm_mask_kernel<<<(n + 511) / 512, 128>>>(h_in, out, n);
    } else {
        generic_scatter_kernel<<<1024, 256>>>(src, E);
        long long total = (long long)n * HF;
        generic_gemm_kernel<<<(int)((total + 255) / 256), 256>>>(
            h_in, W, b, out, n, F_IN, HF);
        generic_maskfix_kernel<<<(n + 255) / 256, 256>>>(out, n, HF);
    }
    (void)n_in; (void)out_size;
}

// round 6
// speedup vs baseline: 3.3817x; 3.3817x over previous
#include <cuda_runtime.h>
#include <cuda_bf16.h>
#include <cstdint>

// ---------------------------------------------------------------------------
// GAT layer, algebraically reduced:
//   Sum_{e: src=n} alpha[e,h] == 1{outdeg(n)>0} in fp32
//   => out = (h_in @ W.T + b) * outdeg_mask
//
// R5 lesson: ptxas here targets sm_103 (no 'a') -> tcgen05 unavailable.
// Use portable mma.sync.m16n8k16 bf16 (sm_80+) with 3-term split
// h1w1 + h2w1 + h1w2 (fp32 accum, ~1.5e-5 rel err).
// ---------------------------------------------------------------------------

#define MASK_CAP (1 << 20)
__device__ unsigned char g_mask[MASK_CAP];        // generic fallback
__device__ unsigned int  g_bits[MASK_CAP / 32];   // fast-path bitmask
// B fragments in mma fragment order: [kiter(24)][nblk(4)][lane(32)] -> uint2
__device__ uint2 g_Bfrag[24 * 4 * 32];

// cvt two fp32 -> packed bf16x2 (lo = first arg in low 16 bits)
__device__ __forceinline__ unsigned cvt2bf(float lo, float hi) {
    unsigned r;
    asm("cvt.rn.bf16x2.f32 %0, %1, %2;" : "=r"(r) : "f"(hi), "f"(lo));
    return r;
}
__device__ __forceinline__ float bf_lo(unsigned p) { return __uint_as_float(p << 16); }
__device__ __forceinline__ float bf_hi(unsigned p) { return __uint_as_float(p & 0xffff0000u); }

__device__ __forceinline__ void ldsm4(unsigned r[4], uint32_t addr) {
    asm volatile("ldmatrix.sync.aligned.m8n8.x4.shared.b16 {%0,%1,%2,%3}, [%4];"
                 : "=r"(r[0]), "=r"(r[1]), "=r"(r[2]), "=r"(r[3]) : "r"(addr));
}
__device__ __forceinline__ void mma_bf16(float c[4], const unsigned a[4],
                                         unsigned b0, unsigned b1) {
    asm volatile("mma.sync.aligned.m16n8k16.row.col.f32.bf16.bf16.f32 "
                 "{%0,%1,%2,%3}, {%4,%5,%6,%7}, {%8,%9}, {%0,%1,%2,%3};"
                 : "+f"(c[0]), "+f"(c[1]), "+f"(c[2]), "+f"(c[3])
                 : "r"(a[0]), "r"(a[1]), "r"(a[2]), "r"(a[3]), "r"(b0), "r"(b1));
}
__device__ __forceinline__ uint32_t smem_u32(const void* p) {
    uint32_t a;
    asm("{ .reg .u64 t; cvta.to.shared.u64 t, %1; cvt.u32.u64 %0, t; }"
        : "=r"(a) : "l"(p));
    return a;
}
// bytes (0/1) of v -> 4 bits
__device__ __forceinline__ unsigned nibb(unsigned v) {
    return (((v & 0x01010101u) * 0x01020408u) >> 24) & 0xFu;
}

// ---------------------------------------------------------------------------
// K1: scatter src -> bitmask (private smem byte-map + atomicOr merge); CTA 0
// also prepares B fragments (w1/w2 bf16 split, mma fragment order).
// Logical K phases: p0=(h1,w1) p1=(h2,w1) p2=(h1,w2); RB = {0,0,1}.
// Fragment map (m16n8k16 row.col): b0 = {B[k][n],B[k+1][n]}, b1 = k+8,
// with n = nb*8 + lane/4, k = (t&7)*16 + (lane&3)*2; B[k][n] = w_RB[n][k].
// ---------------------------------------------------------------------------
__global__ __launch_bounds__(256) void scatter_prep_kernel(
    const int* __restrict__ src, int E, int n, int mapBytes,
    const float* __restrict__ W)
{
    extern __shared__ __align__(16) char dsm[];
    const int tid = threadIdx.x;
    const int g   = gridDim.x;

    if (blockIdx.x == 0) {
        for (int idx = tid; idx < 24 * 4 * 32; idx += 256) {
            int t    = idx >> 7;            // /128
            int rem  = idx & 127;
            int nb   = rem >> 5;
            int lane = rem & 31;
            int p    = t >> 3;
            int rb   = (p == 2) ? 1 : 0;    // 0 -> w1, 1 -> w2
            int nj   = nb * 8 + (lane >> 2);
            int kk   = (t & 7) * 16 + (lane & 3) * 2;
            uint2 fr;
            #pragma unroll
            for (int r = 0; r < 2; ++r) {
                int k = kk + r * 8;
                float x0 = W[nj * 128 + k];
                float x1 = W[nj * 128 + k + 1];
                unsigned p1 = cvt2bf(x0, x1);
                unsigned v;
                if (rb == 0) v = p1;
                else         v = cvt2bf(x0 - bf_lo(p1), x1 - bf_hi(p1));
                if (r == 0) fr.x = v; else fr.y = v;
            }
            g_Bfrag[idx] = fr;
        }
    }

    // zero private byte map
    {
        int4* m4 = reinterpret_cast<int4*>(dsm);
        const int nm4 = mapBytes >> 4;
        for (int i = tid; i < nm4; i += 256) m4[i] = make_int4(0, 0, 0, 0);
    }
    __syncthreads();

    // scatter contiguous edge chunk (plain byte STS)
    {
        const int E4  = E >> 2;
        const int per = (E4 + g - 1) / g;
        const int s4  = blockIdx.x * per;
        const int e4  = min(s4 + per, E4);
        const int4* __restrict__ sp = reinterpret_cast<const int4*>(src);
        for (int i = s4 + tid; i < e4; i += 256) {
            int4 s = sp[i];
            if ((unsigned)s.x < (unsigned)n) dsm[s.x] = 1;
            if ((unsigned)s.y < (unsigned)n) dsm[s.y] = 1;
            if ((unsigned)s.z < (unsigned)n) dsm[s.z] = 1;
            if ((unsigned)s.w < (unsigned)n) dsm[s.w] = 1;
        }
        if (blockIdx.x == g - 1) {
            for (int i = (E4 << 2) + tid; i < E; i += 256) {
                int s = src[i];
                if ((unsigned)s < (unsigned)n) dsm[s] = 1;
            }
        }
    }
    __syncthreads();

    // bit-pack + merge
    {
        const int nWords = (n + 31) >> 5;
        const uint4* mv = reinterpret_cast<const uint4*>(dsm);
        for (int w = tid; w < nWords; w += 256) {
            uint4 a = mv[2 * w + 0];
            uint4 c = mv[2 * w + 1];
            unsigned bits =  nibb(a.x)        | (nibb(a.y) << 4)
                          | (nibb(a.z) << 8)  | (nibb(a.w) << 12)
                          | (nibb(c.x) << 16) | (nibb(c.y) << 20)
                          | (nibb(c.z) << 24) | (nibb(c.w) << 28);
            if (bits) atomicOr(&g_bits[w], bits);
        }
    }
}

// ---------------------------------------------------------------------------
// K2: mma.sync GEMM. Tile = 64 rows x 32 cols, 128 threads (4 warps x 16 rows).
// A smem: [row][h1 256B | h2 256B], pitch 512B, XOR-(row&7)<<4 swizzle.
// Fused bias + mask (+ mask self-clean at kernel start).
// ---------------------------------------------------------------------------
__global__ __launch_bounds__(128) void gemm_mma_kernel(
    const float* __restrict__ h_in,   // [n, 128]
    const float* __restrict__ b,      // [32]
    float* __restrict__ out,          // [n, 32]
    int n)
{
    __shared__ __align__(16) unsigned char As[64 * 512];   // 32KB
    __shared__ float bs[32];
    __shared__ unsigned mb[2];

    const int tid  = threadIdx.x;
    const int w    = tid >> 5;
    const int lane = tid & 31;
    const int tile = blockIdx.x;

    if (tid < 32) bs[tid] = b[tid];
    if (tid < 2) {
        int wi = tile * 2 + tid;
        mb[tid] = g_bits[wi];
        g_bits[wi] = 0;                    // self-clean for next graph replay
    }

    // ---- A: coalesced fp32 row loads -> bf16 split -> swizzled smem ----
    {
        const uint32_t asw = (uint32_t)(lane * 8);
        #pragma unroll 4
        for (int it = 0; it < 16; ++it) {
            int row = w * 16 + it;
            int gr  = tile * 64 + row;
            if (gr >= n) gr = n - 1;       // clamp; stores guarded later
            float4 f4 = reinterpret_cast<const float4*>(h_in + (size_t)gr * 128)[lane];
            unsigned p1a = cvt2bf(f4.x, f4.y);
            unsigned p1b = cvt2bf(f4.z, f4.w);
            unsigned p2a = cvt2bf(f4.x - bf_lo(p1a), f4.y - bf_hi(p1a));
            unsigned p2b = cvt2bf(f4.z - bf_lo(p1b), f4.w - bf_hi(p1b));
            uint32_t sw = (uint32_t)((row & 7) << 4);
            uint32_t o1 = ((uint32_t)(row * 512) + asw) ^ sw;
            uint32_t o2 = ((uint32_t)(row * 512 + 256) + asw) ^ sw;
            *reinterpret_cast<unsigned long long*>(As + o1) =
                (unsigned long long)p1a | ((unsigned long long)p1b << 32);
            *reinterpret_cast<unsigned long long*>(As + o2) =
                (unsigned long long)p2a | ((unsigned long long)p2b << 32);
        }
    }
    __syncthreads();

    // ---- mainloop: 24 k-iters (3 phases x 8), 4 n-blocks each ----
    float acc[4][4] = {};
    const uint32_t As_b = smem_u32(As);
    const int rowl = w * 16 + (lane & 15);
    const uint32_t colh = (uint32_t)((lane >> 4) << 4);
    const uint32_t sw   = (uint32_t)((rowl & 7) << 4);
    const uint2* __restrict__ Bf = g_Bfrag;

    #pragma unroll
    for (int t = 0; t < 24; ++t) {
        const int p  = t >> 3;
        const int ra = (p == 1) ? 1 : 0;   // 0 -> h1, 1 -> h2
        uint32_t off = (uint32_t)(rowl * 512 + ra * 256 + (t & 7) * 32) + colh;
        unsigned a[4];
        ldsm4(a, As_b + (off ^ sw));
        #pragma unroll
        for (int nb = 0; nb < 4; ++nb) {
            uint2 bf = Bf[(t * 4 + nb) * 32 + lane];   // coalesced, L1-hot
            mma_bf16(acc[nb], a, bf.x, bf.y);
        }
    }

    // ---- epilogue: bias + mask + STG.64 ----
    {
        const int rbase = tile * 64 + w * 16;
        const int r0 = rbase + (lane >> 2);
        const int r1 = r0 + 8;
        const unsigned word = mb[w >> 1];
        const float m0 = ((word >> (r0 & 31)) & 1u) ? 1.0f : 0.0f;
        const float m1 = ((word >> (r1 & 31)) & 1u) ? 1.0f : 0.0f;
        const int col = (lane & 3) * 2;
        #pragma unroll
        for (int nb = 0; nb < 4; ++nb) {
            const int c = nb * 8 + col;
            if (r0 < n) {
                float2 v = make_float2((acc[nb][0] + bs[c]) * m0,
                                       (acc[nb][1] + bs[c + 1]) * m0);
                *reinterpret_cast<float2*>(out + (size_t)r0 * 32 + c) = v;
            }
            if (r1 < n) {
                float2 v = make_float2((acc[nb][2] + bs[c]) * m1,
                                       (acc[nb][3] + bs[c + 1]) * m1);
                *reinterpret_cast<float2*>(out + (size_t)r1 * 32 + c) = v;
            }
        }
    }
}

// ---------------------------------------------------------------------------
// Generic fallbacks (any dims) — correctness insurance only.
// ---------------------------------------------------------------------------
__global__ void generic_scatter_kernel(const int* __restrict__ src, int E) {
    int i = blockIdx.x * blockDim.x + threadIdx.x;
    int stride = gridDim.x * blockDim.x;
    for (int e = i; e < E; e += stride) g_mask[src[e]] = 1;
}
__global__ void generic_gemm_kernel(
    const float* __restrict__ h_in, const float* __restrict__ W,
    const float* __restrict__ b, float* __restrict__ out,
    int n, int f_in, int hf)
{
    long long idx = (long long)blockIdx.x * blockDim.x + threadIdx.x;
    if (idx >= (long long)n * hf) return;
    int node = (int)(idx / hf);
    int j    = (int)(idx % hf);
    const float* hr = h_in + (size_t)node * f_in;
    const float* wr = W + (size_t)j * f_in;
    float acc = b[j];
    for (int k = 0; k < f_in; ++k) acc += hr[k] * wr[k];
    out[idx] = acc;
}
__global__ void generic_maskfix_kernel(float* __restrict__ out, int n, int hf) {
    int i = blockIdx.x * blockDim.x + threadIdx.x;
    if (i >= n) return;
    unsigned char m = g_mask[i];
    g_mask[i] = 0;
    if (!m) {
        float* o = out + (size_t)i * hf;
        for (int j = 0; j < hf; ++j) o[j] = 0.0f;
    }
}

extern "C" void kernel_launch(void* const* d_in, const int* in_sizes, int n_in,
                              void* d_out, int out_size) {
    const float* h_in = (const float*)d_in[0];
    const float* W    = (const float*)d_in[1];
    const float* b    = (const float*)d_in[2];
    // d_in[3]=a_src, d_in[4]=a_tgt: provably unused after reduction
    const int* edge_index = (const int*)d_in[5];

    int HF   = in_sizes[2];               // H * F_OUT
    int F_IN = in_sizes[1] / HF;
    int n    = in_sizes[0] / F_IN;
    int E    = in_sizes[5] / 2;
    const int* src = edge_index;          // row 0 of [2, E]

    float* out = (float*)d_out;

    if (F_IN == 128 && HF == 32 && n <= 102400) {
        int mapBytes = (n + 127) & ~127;

        static int inited = 0;
        if (!inited) {
            cudaFuncSetAttribute(scatter_prep_kernel,
                                 cudaFuncAttributeMaxDynamicSharedMemorySize, 104000);
            inited = 1;
        }

        scatter_prep_kernel<<<296, 256, mapBytes>>>(src, E, n, mapBytes, W);
        int tiles = (n + 63) / 64;
        gemm_mma_kernel<<<tiles, 128>>>(h_in, b, out, n);
    } else {
        generic_scatter_kernel<<<1024, 256>>>(src, E);
        long long total = (long long)n * HF;
        generic_gemm_kernel<<<(int)((total + 255) / 256), 256>>>(
            h_in, W, b, out, n, F_IN, HF);
        generic_maskfix_kernel<<<(n + 255) / 256, 256>>>(out, n, HF);
    }
    (void)n_in; (void)out_size;
}

// round 8
// speedup vs baseline: 3.6311x; 1.0738x over previous
#include <cuda_runtime.h>
#include <cuda_bf16.h>
#include <cstdint>

// ---------------------------------------------------------------------------
// GAT layer, algebraically reduced:
//   Sum_{e: src=n} alpha[e,h] == 1{outdeg(n)>0} in fp32
//   => out = (h_in @ W.T + b) * outdeg_mask
//
// mma.sync.m16n8k16 bf16, 3-term split h1w1 + h2w1 + h1w2 (fp32 accum).
// R7 bug: swizzle XOR hoisted before the +t*32 add (carry corrupts XOR bits).
// Fix: XOR applied to the full summed offset (R6 scheme), keep R7 structure:
// single 8-k-iter loop, fragments shared across phases, 2x2 warp tiling,
// B pre-packed as uint4 nb-pairs -> 16 LDG.128 per warp mainloop.
// ---------------------------------------------------------------------------

#define MASK_CAP (1 << 20)
__device__ unsigned char g_mask[MASK_CAP];        // generic fallback
__device__ unsigned int  g_bits[MASK_CAP / 32];   // fast-path bitmask
// B fragments: [split(2)][kiter(8)][nbpair(2)][lane(32)] -> uint4
// uint4 = {b0(nb=2p), b1(nb=2p), b0(nb=2p+1), b1(nb=2p+1)}
__device__ uint4 g_B4[2 * 8 * 2 * 32];

// cvt two fp32 -> packed bf16x2 (lo = first arg in low 16 bits)
__device__ __forceinline__ unsigned cvt2bf(float lo, float hi) {
    unsigned r;
    asm("cvt.rn.bf16x2.f32 %0, %1, %2;" : "=r"(r) : "f"(hi), "f"(lo));
    return r;
}
__device__ __forceinline__ float bf_lo(unsigned p) { return __uint_as_float(p << 16); }
__device__ __forceinline__ float bf_hi(unsigned p) { return __uint_as_float(p & 0xffff0000u); }

__device__ __forceinline__ void ldsm4(unsigned r[4], uint32_t addr) {
    asm volatile("ldmatrix.sync.aligned.m8n8.x4.shared.b16 {%0,%1,%2,%3}, [%4];"
                 : "=r"(r[0]), "=r"(r[1]), "=r"(r[2]), "=r"(r[3]) : "r"(addr));
}
__device__ __forceinline__ void mma_bf16(float c[4], const unsigned a[4],
                                         unsigned b0, unsigned b1) {
    asm volatile("mma.sync.aligned.m16n8k16.row.col.f32.bf16.bf16.f32 "
                 "{%0,%1,%2,%3}, {%4,%5,%6,%7}, {%8,%9}, {%0,%1,%2,%3};"
                 : "+f"(c[0]), "+f"(c[1]), "+f"(c[2]), "+f"(c[3])
                 : "r"(a[0]), "r"(a[1]), "r"(a[2]), "r"(a[3]), "r"(b0), "r"(b1));
}
__device__ __forceinline__ uint32_t smem_u32(const void* p) {
    uint32_t a;
    asm("{ .reg .u64 t; cvta.to.shared.u64 t, %1; cvt.u32.u64 %0, t; }"
        : "=r"(a) : "l"(p));
    return a;
}
// bytes (0/1) of v -> 4 bits
__device__ __forceinline__ unsigned nibb(unsigned v) {
    return (((v & 0x01010101u) * 0x01020408u) >> 24) & 0xFu;
}

// ---------------------------------------------------------------------------
// K1: scatter src -> bitmask; CTA 0 prepares B fragment pairs (w1/w2 split).
// Fragment map (m16n8k16 row.col): for (split s, kiter t, nb, lane):
//   nj = nb*8 + lane/4, kk = t*16 + (lane&3)*2; b0 from k=kk, b1 from k=kk+8
//   s=0 -> bf16(W), s=1 -> bf16(W - bf16(W))
// ---------------------------------------------------------------------------
__global__ __launch_bounds__(256) void scatter_prep_kernel(
    const int* __restrict__ src, int E, int n, int mapBytes,
    const float* __restrict__ W)
{
    extern __shared__ __align__(16) char dsm[];
    const int tid = threadIdx.x;
    const int g   = gridDim.x;

    if (blockIdx.x == 0) {
        for (int idx = tid; idx < 2 * 8 * 2 * 32; idx += 256) {
            int s    = idx >> 9;
            int t    = (idx >> 6) & 7;
            int p    = (idx >> 5) & 1;
            int lane = idx & 31;
            unsigned fr[2][2];
            #pragma unroll
            for (int i = 0; i < 2; ++i) {
                int nb = 2 * p + i;
                int nj = nb * 8 + (lane >> 2);
                int kk = t * 16 + (lane & 3) * 2;
                #pragma unroll
                for (int r = 0; r < 2; ++r) {
                    int k = kk + r * 8;
                    float x0 = W[nj * 128 + k];
                    float x1 = W[nj * 128 + k + 1];
                    unsigned p1 = cvt2bf(x0, x1);
                    fr[i][r] = (s == 0) ? p1
                             : cvt2bf(x0 - bf_lo(p1), x1 - bf_hi(p1));
                }
            }
            uint4 v = make_uint4(fr[0][0], fr[0][1], fr[1][0], fr[1][1]);
            g_B4[idx] = v;
        }
    }

    // zero private byte map
    {
        int4* m4 = reinterpret_cast<int4*>(dsm);
        const int nm4 = mapBytes >> 4;
        for (int i = tid; i < nm4; i += 256) m4[i] = make_int4(0, 0, 0, 0);
    }
    __syncthreads();

    // scatter contiguous edge chunk (plain byte STS)
    {
        const int E4  = E >> 2;
        const int per = (E4 + g - 1) / g;
        const int s4  = blockIdx.x * per;
        const int e4  = min(s4 + per, E4);
        const int4* __restrict__ sp = reinterpret_cast<const int4*>(src);
        for (int i = s4 + tid; i < e4; i += 256) {
            int4 s = sp[i];
            if ((unsigned)s.x < (unsigned)n) dsm[s.x] = 1;
            if ((unsigned)s.y < (unsigned)n) dsm[s.y] = 1;
            if ((unsigned)s.z < (unsigned)n) dsm[s.z] = 1;
            if ((unsigned)s.w < (unsigned)n) dsm[s.w] = 1;
        }
        if (blockIdx.x == g - 1) {
            for (int i = (E4 << 2) + tid; i < E; i += 256) {
                int s = src[i];
                if ((unsigned)s < (unsigned)n) dsm[s] = 1;
            }
        }
    }
    __syncthreads();

    // bit-pack + merge
    {
        const int nWords = (n + 31) >> 5;
        const uint4* mv = reinterpret_cast<const uint4*>(dsm);
        for (int w = tid; w < nWords; w += 256) {
            uint4 a = mv[2 * w + 0];
            uint4 c = mv[2 * w + 1];
            unsigned bits =  nibb(a.x)        | (nibb(a.y) << 4)
                          | (nibb(a.z) << 8)  | (nibb(a.w) << 12)
                          | (nibb(c.x) << 16) | (nibb(c.y) << 20)
                          | (nibb(c.z) << 24) | (nibb(c.w) << 28);
            if (bits) atomicOr(&g_bits[w], bits);
        }
    }
}

// ---------------------------------------------------------------------------
// K2: mma.sync GEMM. Tile = 64 rows x 32 cols, 128 threads.
// Warp tiling 2x2: warp w -> mhalf = w&1 (rows mhalf*32, 2 m16 blocks),
//                             npair = w>>1 (cols npair*16, 2 n8 blocks).
// A smem: [row][h1 256B | h2 256B], pitch 512B, XOR-(row&7)<<4 swizzle
// applied to the FULL byte offset (store and load identically).
// ---------------------------------------------------------------------------
__global__ __launch_bounds__(128) void gemm_mma_kernel(
    const float* __restrict__ h_in,   // [n, 128]
    const float* __restrict__ b,      // [32]
    float* __restrict__ out,          // [n, 32]
    int n)
{
    __shared__ __align__(16) unsigned char As[64 * 512];   // 32KB
    __shared__ float bs[32];
    __shared__ unsigned mb[2];

    const int tid  = threadIdx.x;
    const int w    = tid >> 5;
    const int lane = tid & 31;
    const int tile = blockIdx.x;

    if (tid < 32) bs[tid] = b[tid];
    if (tid < 2) {
        int wi = tile * 2 + tid;
        mb[tid] = g_bits[wi];
        g_bits[wi] = 0;                    // self-clean for next graph replay
    }

    // ---- A: coalesced fp32 row loads -> bf16 split -> swizzled smem ----
    {
        const uint32_t asw = (uint32_t)(lane * 8);
        #pragma unroll 4
        for (int it = 0; it < 16; ++it) {
            int row = w * 16 + it;
            int gr  = tile * 64 + row;
            if (gr >= n) gr = n - 1;       // clamp; stores guarded later
            float4 f4 = reinterpret_cast<const float4*>(h_in + (size_t)gr * 128)[lane];
            unsigned p1a = cvt2bf(f4.x, f4.y);
            unsigned p1b = cvt2bf(f4.z, f4.w);
            unsigned p2a = cvt2bf(f4.x - bf_lo(p1a), f4.y - bf_hi(p1a));
            unsigned p2b = cvt2bf(f4.z - bf_lo(p1b), f4.w - bf_hi(p1b));
            uint32_t sw = (uint32_t)((row & 7) << 4);
            uint32_t o1 = ((uint32_t)(row * 512) + asw) ^ sw;
            uint32_t o2 = ((uint32_t)(row * 512 + 256) + asw) ^ sw;
            *reinterpret_cast<unsigned long long*>(As + o1) =
                (unsigned long long)p1a | ((unsigned long long)p1b << 32);
            *reinterpret_cast<unsigned long long*>(As + o2) =
                (unsigned long long)p2a | ((unsigned long long)p2b << 32);
        }
    }
    __syncthreads();

    // ---- mainloop: 8 k-iters, fragments shared across the 3 split-phases ----
    const int mhalf = w & 1;               // which 32-row half
    const int npair = w >> 1;              // which 16-col pair
    float acc[2][2][4] = {};               // [mblk][nblk][frag]

    const uint32_t As_b = smem_u32(As);
    const uint32_t colh = (uint32_t)((lane >> 4) << 4);
    const uint32_t sw   = (uint32_t)((lane & 7) << 4);   // == (rowl&7)<<4, both m
    uint32_t aoff[2];                       // un-swizzled base offsets
    #pragma unroll
    for (int m = 0; m < 2; ++m) {
        int rowl = mhalf * 32 + m * 16 + (lane & 15);
        aoff[m] = (uint32_t)(rowl * 512) + colh;
    }
    const uint4* __restrict__ Bp = g_B4 + npair * 32 + lane;

    #pragma unroll
    for (int t = 0; t < 8; ++t) {
        unsigned a1[2][4], a2[2][4];
        #pragma unroll
        for (int m = 0; m < 2; ++m) {
            // XOR applied to the FULL offset (swizzle-correct)
            ldsm4(a1[m], As_b + ((aoff[m] + (uint32_t)(t * 32)) ^ sw));        // h1
            ldsm4(a2[m], As_b + ((aoff[m] + (uint32_t)(256 + t * 32)) ^ sw));  // h2
        }
        uint4 bw1 = Bp[(t * 2) * 32];            // w1 frags, nb pair
        uint4 bw2 = Bp[(16 + t * 2) * 32];       // w2 frags, nb pair
        #pragma unroll
        for (int m = 0; m < 2; ++m) {
            mma_bf16(acc[m][0], a1[m], bw1.x, bw1.y);   // h1*w1
            mma_bf16(acc[m][1], a1[m], bw1.z, bw1.w);
            mma_bf16(acc[m][0], a2[m], bw1.x, bw1.y);   // h2*w1
            mma_bf16(acc[m][1], a2[m], bw1.z, bw1.w);
            mma_bf16(acc[m][0], a1[m], bw2.x, bw2.y);   // h1*w2
            mma_bf16(acc[m][1], a1[m], bw2.z, bw2.w);
        }
    }

    // ---- epilogue: bias + mask + STG.64 ----
    {
        const unsigned word = mb[mhalf];           // warp-uniform mask word
        #pragma unroll
        for (int m = 0; m < 2; ++m) {
            const int rt0 = mhalf * 32 + m * 16 + (lane >> 2);  // in-tile row
            const int r0  = tile * 64 + rt0;
            const int r1  = r0 + 8;
            const float m0 = ((word >> (rt0 & 31)) & 1u) ? 1.0f : 0.0f;
            const float m1 = ((word >> ((rt0 + 8) & 31)) & 1u) ? 1.0f : 0.0f;
            #pragma unroll
            for (int i = 0; i < 2; ++i) {
                const int c = (2 * npair + i) * 8 + (lane & 3) * 2;
                if (r0 < n) {
                    float2 v = make_float2((acc[m][i][0] + bs[c]) * m0,
                                           (acc[m][i][1] + bs[c + 1]) * m0);
                    *reinterpret_cast<float2*>(out + (size_t)r0 * 32 + c) = v;
                }
                if (r1 < n) {
                    float2 v = make_float2((acc[m][i][2] + bs[c]) * m1,
                                           (acc[m][i][3] + bs[c + 1]) * m1);
                    *reinterpret_cast<float2*>(out + (size_t)r1 * 32 + c) = v;
                }
            }
        }
    }
}

// ---------------------------------------------------------------------------
// Generic fallbacks (any dims) — correctness insurance only.
// ---------------------------------------------------------------------------
__global__ void generic_scatter_kernel(const int* __restrict__ src, int E) {
    int i = blockIdx.x * blockDim.x + threadIdx.x;
    int stride = gridDim.x * blockDim.x;
    for (int e = i; e < E; e += stride) g_mask[src[e]] = 1;
}
__global__ void generic_gemm_kernel(
    const float* __restrict__ h_in, const float* __restrict__ W,
    const float* __restrict__ b, float* __restrict__ out,
    int n, int f_in, int hf)
{
    long long idx = (long long)blockIdx.x * blockDim.x + threadIdx.x;
    if (idx >= (long long)n * hf) return;
    int node = (int)(idx / hf);
    int j    = (int)(idx % hf);
    const float* hr = h_in + (size_t)node * f_in;
    const float* wr = W + (size_t)j * f_in;
    float acc = b[j];
    for (int k = 0; k < f_in; ++k) acc += hr[k] * wr[k];
    out[idx] = acc;
}
__global__ void generic_maskfix_kernel(float* __restrict__ out, int n, int hf) {
    int i = blockIdx.x * blockDim.x + threadIdx.x;
    if (i >= n) return;
    unsigned char m = g_mask[i];
    g_mask[i] = 0;
    if (!m) {
        float* o = out + (size_t)i * hf;
        for (int j = 0; j < hf; ++j) o[j] = 0.0f;
    }
}

extern "C" void kernel_launch(void* const* d_in, const int* in_sizes, int n_in,
                              void* d_out, int out_size) {
    const float* h_in = (const float*)d_in[0];
    const float* W    = (const float*)d_in[1];
    const float* b    = (const float*)d_in[2];
    // d_in[3]=a_src, d_in[4]=a_tgt: provably unused after reduction
    const int* edge_index = (const int*)d_in[5];

    int HF   = in_sizes[2];               // H * F_OUT
    int F_IN = in_sizes[1] / HF;
    int n    = in_sizes[0] / F_IN;
    int E    = in_sizes[5] / 2;
    const int* src = edge_index;          // row 0 of [2, E]

    float* out = (float*)d_out;

    if (F_IN == 128 && HF == 32 && n <= 102400) {
        int mapBytes = (n + 127) & ~127;

        static int inited = 0;
        if (!inited) {
            cudaFuncSetAttribute(scatter_prep_kernel,
                                 cudaFuncAttributeMaxDynamicSharedMemorySize, 104000);
            inited = 1;
        }

        scatter_prep_kernel<<<296, 256, mapBytes>>>(src, E, n, mapBytes, W);
        int tiles = (n + 63) / 64;
        gemm_mma_kernel<<<tiles, 128>>>(h_in, b, out, n);
    } else {
        generic_scatter_kernel<<<1024, 256>>>(src, E);
        long long total = (long long)n * HF;
        generic_gemm_kernel<<<(int)((total + 255) / 256), 256>>>(
            h_in, W, b, out, n, F_IN, HF);
        generic_maskfix_kernel<<<(n + 255) / 256, 256>>>(out, n, HF);
    }
    (void)n_in; (void)out_size;
}

// round 9
// speedup vs baseline: 3.6725x; 1.0114x over previous
#include <cuda_runtime.h>
#include <cuda_bf16.h>
#include <cstdint>

// ---------------------------------------------------------------------------
// GAT layer, algebraically reduced:
//   Sum_{e: src=n} alpha[e,h] == 1{outdeg(n)>0} in fp32
//   => out = (h_in @ W.T + b) * outdeg_mask
//
// mma.sync.m16n8k16 bf16, 3-term split h1w1 + h2w1 + h1w2 (fp32 accum).
// R8 lesson: A-load phase was dependent-LDG latency-bound (issue 17%).
// R9: cp.async raw fp32 tile -> smem (unbounded MLP, no reg chains), then
// in-place warp-synchronous convert (fp32 row 512B == split row 512B), so
// smem stays 32KB and occupancy stays 6 CTAs/SM. Mainloop identical to R8.
// ---------------------------------------------------------------------------

#define MASK_CAP (1 << 20)
__device__ unsigned char g_mask[MASK_CAP];        // generic fallback
__device__ unsigned int  g_bits[MASK_CAP / 32];   // fast-path bitmask
// B fragments: [split(2)][kiter(8)][nbpair(2)][lane(32)] -> uint4
// uint4 = {b0(nb=2p), b1(nb=2p), b0(nb=2p+1), b1(nb=2p+1)}
__device__ uint4 g_B4[2 * 8 * 2 * 32];

// cvt two fp32 -> packed bf16x2 (lo = first arg in low 16 bits)
__device__ __forceinline__ unsigned cvt2bf(float lo, float hi) {
    unsigned r;
    asm("cvt.rn.bf16x2.f32 %0, %1, %2;" : "=r"(r) : "f"(hi), "f"(lo));
    return r;
}
__device__ __forceinline__ float bf_lo(unsigned p) { return __uint_as_float(p << 16); }
__device__ __forceinline__ float bf_hi(unsigned p) { return __uint_as_float(p & 0xffff0000u); }

__device__ __forceinline__ void ldsm4(unsigned r[4], uint32_t addr) {
    asm volatile("ldmatrix.sync.aligned.m8n8.x4.shared.b16 {%0,%1,%2,%3}, [%4];"
                 : "=r"(r[0]), "=r"(r[1]), "=r"(r[2]), "=r"(r[3]) : "r"(addr));
}
__device__ __forceinline__ void mma_bf16(float c[4], const unsigned a[4],
                                         unsigned b0, unsigned b1) {
    asm volatile("mma.sync.aligned.m16n8k16.row.col.f32.bf16.bf16.f32 "
                 "{%0,%1,%2,%3}, {%4,%5,%6,%7}, {%8,%9}, {%0,%1,%2,%3};"
                 : "+f"(c[0]), "+f"(c[1]), "+f"(c[2]), "+f"(c[3])
                 : "r"(a[0]), "r"(a[1]), "r"(a[2]), "r"(a[3]), "r"(b0), "r"(b1));
}
__device__ __forceinline__ uint32_t smem_u32(const void* p) {
    uint32_t a;
    asm("{ .reg .u64 t; cvta.to.shared.u64 t, %1; cvt.u32.u64 %0, t; }"
        : "=r"(a) : "l"(p));
    return a;
}
// bytes (0/1) of v -> 4 bits
__device__ __forceinline__ unsigned nibb(unsigned v) {
    return (((v & 0x01010101u) * 0x01020408u) >> 24) & 0xFu;
}

// ---------------------------------------------------------------------------
// K1: scatter src -> bitmask; CTA 0 prepares B fragment pairs (w1/w2 split).
// ---------------------------------------------------------------------------
__global__ __launch_bounds__(256) void scatter_prep_kernel(
    const int* __restrict__ src, int E, int n, int mapBytes,
    const float* __restrict__ W)
{
    extern __shared__ __align__(16) char dsm[];
    const int tid = threadIdx.x;
    const int g   = gridDim.x;

    if (blockIdx.x == 0) {
        for (int idx = tid; idx < 2 * 8 * 2 * 32; idx += 256) {
            int s    = idx >> 9;
            int t    = (idx >> 6) & 7;
            int p    = (idx >> 5) & 1;
            int lane = idx & 31;
            unsigned fr[2][2];
            #pragma unroll
            for (int i = 0; i < 2; ++i) {
                int nb = 2 * p + i;
                int nj = nb * 8 + (lane >> 2);
                int kk = t * 16 + (lane & 3) * 2;
                #pragma unroll
                for (int r = 0; r < 2; ++r) {
                    int k = kk + r * 8;
                    float x0 = W[nj * 128 + k];
                    float x1 = W[nj * 128 + k + 1];
                    unsigned p1 = cvt2bf(x0, x1);
                    fr[i][r] = (s == 0) ? p1
                             : cvt2bf(x0 - bf_lo(p1), x1 - bf_hi(p1));
                }
            }
            uint4 v = make_uint4(fr[0][0], fr[0][1], fr[1][0], fr[1][1]);
            g_B4[idx] = v;
        }
    }

    // zero private byte map
    {
        int4* m4 = reinterpret_cast<int4*>(dsm);
        const int nm4 = mapBytes >> 4;
        for (int i = tid; i < nm4; i += 256) m4[i] = make_int4(0, 0, 0, 0);
    }
    __syncthreads();

    // scatter contiguous edge chunk (plain byte STS)
    {
        const int E4  = E >> 2;
        const int per = (E4 + g - 1) / g;
        const int s4  = blockIdx.x * per;
        const int e4  = min(s4 + per, E4);
        const int4* __restrict__ sp = reinterpret_cast<const int4*>(src);
        for (int i = s4 + tid; i < e4; i += 256) {
            int4 s = sp[i];
            if ((unsigned)s.x < (unsigned)n) dsm[s.x] = 1;
            if ((unsigned)s.y < (unsigned)n) dsm[s.y] = 1;
            if ((unsigned)s.z < (unsigned)n) dsm[s.z] = 1;
            if ((unsigned)s.w < (unsigned)n) dsm[s.w] = 1;
        }
        if (blockIdx.x == g - 1) {
            for (int i = (E4 << 2) + tid; i < E; i += 256) {
                int s = src[i];
                if ((unsigned)s < (unsigned)n) dsm[s] = 1;
            }
        }
    }
    __syncthreads();

    // bit-pack + merge
    {
        const int nWords = (n + 31) >> 5;
        const uint4* mv = reinterpret_cast<const uint4*>(dsm);
        for (int w = tid; w < nWords; w += 256) {
            uint4 a = mv[2 * w + 0];
            uint4 c = mv[2 * w + 1];
            unsigned bits =  nibb(a.x)        | (nibb(a.y) << 4)
                          | (nibb(a.z) << 8)  | (nibb(a.w) << 12)
                          | (nibb(c.x) << 16) | (nibb(c.y) << 20)
                          | (nibb(c.z) << 24) | (nibb(c.w) << 28);
            if (bits) atomicOr(&g_bits[w], bits);
        }
    }
}

// ---------------------------------------------------------------------------
// K2: mma.sync GEMM. Tile = 64 rows x 32 cols, 128 threads, 2x2 warp tiling.
// A smem: [row][h1 256B | h2 256B], pitch 512B, XOR-(row&7)<<4 swizzle on the
// full byte offset. Raw fp32 staged via cp.async into the SAME buffer, then
// converted in place (warp owns its rows; intra-warp order guarantees safety).
// ---------------------------------------------------------------------------
__global__ __launch_bounds__(128) void gemm_mma_kernel(
    const float* __restrict__ h_in,   // [n, 128]
    const float* __restrict__ b,      // [32]
    float* __restrict__ out,          // [n, 32]
    int n)
{
    __shared__ __align__(16) unsigned char As[64 * 512];   // 32KB
    __shared__ float bs[32];
    __shared__ unsigned mb[2];

    const int tid  = threadIdx.x;
    const int w    = tid >> 5;
    const int lane = tid & 31;
    const int tile = blockIdx.x;
    const uint32_t As_b = smem_u32(As);

    if (tid < 32) bs[tid] = b[tid];
    if (tid < 2) {
        int wi = tile * 2 + tid;
        mb[tid] = g_bits[wi];
        g_bits[wi] = 0;                    // self-clean for next graph replay
    }

    // ---- phase 1: cp.async raw fp32 rows -> swizzled smem (own rows) ----
    {
        #pragma unroll
        for (int it = 0; it < 16; ++it) {
            int row = w * 16 + it;
            int gr  = tile * 64 + row;
            if (gr >= n) gr = n - 1;       // clamp; stores guarded later
            const char* srcp = reinterpret_cast<const char*>(h_in) +
                               (size_t)gr * 512 + (size_t)(lane * 16);
            uint32_t dst = As_b +
                ((((uint32_t)(row * 512)) + (uint32_t)(lane * 16)) ^
                 ((uint32_t)((row & 7) << 4)));
            asm volatile("cp.async.cg.shared.global [%0], [%1], 16;"
                         :: "r"(dst), "l"(srcp) : "memory");
        }
        asm volatile("cp.async.commit_group;" ::: "memory");
        asm volatile("cp.async.wait_group 0;" ::: "memory");
    }

    // ---- phase 2: in-place convert fp32 row -> (h1 | h2) bf16 halves ----
    // Each lane reads exactly the 16B chunk it cp.async'd; writes 8B to the
    // h1 half and 8B to the h2 half of the same row. LDS->cvt->STS data
    // dependency orders the read before any lane's write within the warp.
    {
        #pragma unroll 4
        for (int it = 0; it < 16; ++it) {
            int row = w * 16 + it;
            uint32_t sw = (uint32_t)((row & 7) << 4);
            uint32_t ro = (uint32_t)(row * 512);
            float4 f4;
            asm volatile("ld.shared.v4.f32 {%0,%1,%2,%3}, [%4];"
                         : "=f"(f4.x), "=f"(f4.y), "=f"(f4.z), "=f"(f4.w)
                         : "r"(As_b + ((ro + (uint32_t)(lane * 16)) ^ sw)));
            unsigned p1a = cvt2bf(f4.x, f4.y);
            unsigned p1b = cvt2bf(f4.z, f4.w);
            unsigned p2a = cvt2bf(f4.x - bf_lo(p1a), f4.y - bf_hi(p1a));
            unsigned p2b = cvt2bf(f4.z - bf_lo(p1b), f4.w - bf_hi(p1b));
            unsigned long long v1 =
                (unsigned long long)p1a | ((unsigned long long)p1b << 32);
            unsigned long long v2 =
                (unsigned long long)p2a | ((unsigned long long)p2b << 32);
            asm volatile("st.shared.b64 [%0], %1;"
                         :: "r"(As_b + ((ro + (uint32_t)(lane * 8)) ^ sw)), "l"(v1)
                         : "memory");
            asm volatile("st.shared.b64 [%0], %1;"
                         :: "r"(As_b + ((ro + 256u + (uint32_t)(lane * 8)) ^ sw)), "l"(v2)
                         : "memory");
        }
    }
    __syncthreads();

    // ---- mainloop: 8 k-iters, fragments shared across the 3 split-phases ----
    const int mhalf = w & 1;               // which 32-row half
    const int npair = w >> 1;              // which 16-col pair
    float acc[2][2][4] = {};               // [mblk][nblk][frag]

    const uint32_t colh = (uint32_t)((lane >> 4) << 4);
    const uint32_t sw   = (uint32_t)((lane & 7) << 4);   // == (rowl&7)<<4, both m
    uint32_t aoff[2];                       // un-swizzled base offsets
    #pragma unroll
    for (int m = 0; m < 2; ++m) {
        int rowl = mhalf * 32 + m * 16 + (lane & 15);
        aoff[m] = (uint32_t)(rowl * 512) + colh;
    }
    const uint4* __restrict__ Bp = g_B4 + npair * 32 + lane;

    #pragma unroll
    for (int t = 0; t < 8; ++t) {
        unsigned a1[2][4], a2[2][4];
        #pragma unroll
        for (int m = 0; m < 2; ++m) {
            // XOR applied to the FULL offset (swizzle-correct)
            ldsm4(a1[m], As_b + ((aoff[m] + (uint32_t)(t * 32)) ^ sw));        // h1
            ldsm4(a2[m], As_b + ((aoff[m] + (uint32_t)(256 + t * 32)) ^ sw));  // h2
        }
        uint4 bw1 = Bp[(t * 2) * 32];            // w1 frags, nb pair
        uint4 bw2 = Bp[(16 + t * 2) * 32];       // w2 frags, nb pair
        #pragma unroll
        for (int m = 0; m < 2; ++m) {
            mma_bf16(acc[m][0], a1[m], bw1.x, bw1.y);   // h1*w1
            mma_bf16(acc[m][1], a1[m], bw1.z, bw1.w);
            mma_bf16(acc[m][0], a2[m], bw1.x, bw1.y);   // h2*w1
            mma_bf16(acc[m][1], a2[m], bw1.z, bw1.w);
            mma_bf16(acc[m][0], a1[m], bw2.x, bw2.y);   // h1*w2
            mma_bf16(acc[m][1], a1[m], bw2.z, bw2.w);
        }
    }

    // ---- epilogue: bias + mask + STG.64 ----
    {
        const unsigned word = mb[mhalf];           // warp-uniform mask word
        #pragma unroll
        for (int m = 0; m < 2; ++m) {
            const int rt0 = mhalf * 32 + m * 16 + (lane >> 2);  // in-tile row
            const int r0  = tile * 64 + rt0;
            const int r1  = r0 + 8;
            const float m0 = ((word >> (rt0 & 31)) & 1u) ? 1.0f : 0.0f;
            const float m1 = ((word >> ((rt0 + 8) & 31)) & 1u) ? 1.0f : 0.0f;
            #pragma unroll
            for (int i = 0; i < 2; ++i) {
                const int c = (2 * npair + i) * 8 + (lane & 3) * 2;
                if (r0 < n) {
                    float2 v = make_float2((acc[m][i][0] + bs[c]) * m0,
                                           (acc[m][i][1] + bs[c + 1]) * m0);
                    *reinterpret_cast<float2*>(out + (size_t)r0 * 32 + c) = v;
                }
                if (r1 < n) {
                    float2 v = make_float2((acc[m][i][2] + bs[c]) * m1,
                                           (acc[m][i][3] + bs[c + 1]) * m1);
                    *reinterpret_cast<float2*>(out + (size_t)r1 * 32 + c) = v;
                }
            }
        }
    }
}

// ---------------------------------------------------------------------------
// Generic fallbacks (any dims) — correctness insurance only.
// ---------------------------------------------------------------------------
__global__ void generic_scatter_kernel(const int* __restrict__ src, int E) {
    int i = blockIdx.x * blockDim.x + threadIdx.x;
    int stride = gridDim.x * blockDim.x;
    for (int e = i; e < E; e += stride) g_mask[src[e]] = 1;
}
__global__ void generic_gemm_kernel(
    const float* __restrict__ h_in, const float* __restrict__ W,
    const float* __restrict__ b, float* __restrict__ out,
    int n, int f_in, int hf)
{
    long long idx = (long long)blockIdx.x * blockDim.x + threadIdx.x;
    if (idx >= (long long)n * hf) return;
    int node = (int)(idx / hf);
    int j    = (int)(idx % hf);
    const float* hr = h_in + (size_t)node * f_in;
    const float* wr = W + (size_t)j * f_in;
    float acc = b[j];
    for (int k = 0; k < f_in; ++k) acc += hr[k] * wr[k];
    out[idx] = acc;
}
__global__ void generic_maskfix_kernel(float* __restrict__ out, int n, int hf) {
    int i = blockIdx.x * blockDim.x + threadIdx.x;
    if (i >= n) return;
    unsigned char m = g_mask[i];
    g_mask[i] = 0;
    if (!m) {
        float* o = out + (size_t)i * hf;
        for (int j = 0; j < hf; ++j) o[j] = 0.0f;
    }
}

extern "C" void kernel_launch(void* const* d_in, const int* in_sizes, int n_in,
                              void* d_out, int out_size) {
    const float* h_in = (const float*)d_in[0];
    const float* W    = (const float*)d_in[1];
    const float* b    = (const float*)d_in[2];
    // d_in[3]=a_src, d_in[4]=a_tgt: provably unused after reduction
    const int* edge_index = (const int*)d_in[5];

    int HF   = in_sizes[2];               // H * F_OUT
    int F_IN = in_sizes[1] / HF;
    int n    = in_sizes[0] / F_IN;
    int E    = in_sizes[5] / 2;
    const int* src = edge_index;          // row 0 of [2, E]

    float* out = (float*)d_out;

    if (F_IN == 128 && HF == 32 && n <= 102400) {
        int mapBytes = (n + 127) & ~127;

        static int inited = 0;
        if (!inited) {
            cudaFuncSetAttribute(scatter_prep_kernel,
                                 cudaFuncAttributeMaxDynamicSharedMemorySize, 104000);
            inited = 1;
        }

        scatter_prep_kernel<<<296, 256, mapBytes>>>(src, E, n, mapBytes, W);
        int tiles = (n + 63) / 64;
        gemm_mma_kernel<<<tiles, 128>>>(h_in, b, out, n);
    } else {
        generic_scatter_kernel<<<1024, 256>>>(src, E);
        long long total = (long long)n * HF;
        generic_gemm_kernel<<<(int)((total + 255) / 256), 256>>>(
            h_in, W, b, out, n, F_IN, HF);
        generic_maskfix_kernel<<<(n + 255) / 256, 256>>>(out, n, HF);
    }
    (void)n_in; (void)out_size;
}

// round 10
// speedup vs baseline: 4.1792x; 1.1380x over previous
#include <cuda_runtime.h>
#include <cuda_bf16.h>
#include <cstdint>

// ---------------------------------------------------------------------------
// GAT layer, algebraically reduced:
//   Sum_{e: src=n} alpha[e,h] == 1{outdeg(n)>0} in fp32
//   => out = (h_in @ W.T + b) * outdeg_mask
//
// mma.sync.m16n8k16 bf16, 3-term split h1w1 + h2w1 + h1w2 (fp32 accum).
// R9 lesson: the post-convert __syncthreads coupled all warps to the slowest
// DRAM wait. R10: warp-independent tiling — warp w owns m16 block w (the same
// 16 rows it cp.asyncs + converts) and all 4 n-blocks, so the barrier between
// convert and mainloop is gone. Only one cheap early barrier (bias+mask smem).
// ---------------------------------------------------------------------------

#define MASK_CAP (1 << 20)
__device__ unsigned char g_mask[MASK_CAP];        // generic fallback
__device__ unsigned int  g_bits[MASK_CAP / 32];   // fast-path bitmask
// B fragments: [split(2)][kiter(8)][nbpair(2)][lane(32)] -> uint4
// uint4 = {b0(nb=2p), b1(nb=2p), b0(nb=2p+1), b1(nb=2p+1)}
__device__ uint4 g_B4[2 * 8 * 2 * 32];

// cvt two fp32 -> packed bf16x2 (lo = first arg in low 16 bits)
__device__ __forceinline__ unsigned cvt2bf(float lo, float hi) {
    unsigned r;
    asm("cvt.rn.bf16x2.f32 %0, %1, %2;" : "=r"(r) : "f"(hi), "f"(lo));
    return r;
}
__device__ __forceinline__ float bf_lo(unsigned p) { return __uint_as_float(p << 16); }
__device__ __forceinline__ float bf_hi(unsigned p) { return __uint_as_float(p & 0xffff0000u); }

__device__ __forceinline__ void ldsm4(unsigned r[4], uint32_t addr) {
    asm volatile("ldmatrix.sync.aligned.m8n8.x4.shared.b16 {%0,%1,%2,%3}, [%4];"
                 : "=r"(r[0]), "=r"(r[1]), "=r"(r[2]), "=r"(r[3]) : "r"(addr));
}
__device__ __forceinline__ void mma_bf16(float c[4], const unsigned a[4],
                                         unsigned b0, unsigned b1) {
    asm volatile("mma.sync.aligned.m16n8k16.row.col.f32.bf16.bf16.f32 "
                 "{%0,%1,%2,%3}, {%4,%5,%6,%7}, {%8,%9}, {%0,%1,%2,%3};"
                 : "+f"(c[0]), "+f"(c[1]), "+f"(c[2]), "+f"(c[3])
                 : "r"(a[0]), "r"(a[1]), "r"(a[2]), "r"(a[3]), "r"(b0), "r"(b1));
}
__device__ __forceinline__ uint32_t smem_u32(const void* p) {
    uint32_t a;
    asm("{ .reg .u64 t; cvta.to.shared.u64 t, %1; cvt.u32.u64 %0, t; }"
        : "=r"(a) : "l"(p));
    return a;
}
// bytes (0/1) of v -> 4 bits
__device__ __forceinline__ unsigned nibb(unsigned v) {
    return (((v & 0x01010101u) * 0x01020408u) >> 24) & 0xFu;
}

// ---------------------------------------------------------------------------
// K1: scatter src -> bitmask; CTA 0 prepares B fragment pairs (w1/w2 split).
// ---------------------------------------------------------------------------
__global__ __launch_bounds__(256) void scatter_prep_kernel(
    const int* __restrict__ src, int E, int n, int mapBytes,
    const float* __restrict__ W)
{
    extern __shared__ __align__(16) char dsm[];
    const int tid = threadIdx.x;
    const int g   = gridDim.x;

    if (blockIdx.x == 0) {
        for (int idx = tid; idx < 2 * 8 * 2 * 32; idx += 256) {
            int s    = idx >> 9;
            int t    = (idx >> 6) & 7;
            int p    = (idx >> 5) & 1;
            int lane = idx & 31;
            unsigned fr[2][2];
            #pragma unroll
            for (int i = 0; i < 2; ++i) {
                int nb = 2 * p + i;
                int nj = nb * 8 + (lane >> 2);
                int kk = t * 16 + (lane & 3) * 2;
                #pragma unroll
                for (int r = 0; r < 2; ++r) {
                    int k = kk + r * 8;
                    float x0 = W[nj * 128 + k];
                    float x1 = W[nj * 128 + k + 1];
                    unsigned p1 = cvt2bf(x0, x1);
                    fr[i][r] = (s == 0) ? p1
                             : cvt2bf(x0 - bf_lo(p1), x1 - bf_hi(p1));
                }
            }
            uint4 v = make_uint4(fr[0][0], fr[0][1], fr[1][0], fr[1][1]);
            g_B4[idx] = v;
        }
    }

    // zero private byte map
    {
        int4* m4 = reinterpret_cast<int4*>(dsm);
        const int nm4 = mapBytes >> 4;
        for (int i = tid; i < nm4; i += 256) m4[i] = make_int4(0, 0, 0, 0);
    }
    __syncthreads();

    // scatter contiguous edge chunk (plain byte STS)
    {
        const int E4  = E >> 2;
        const int per = (E4 + g - 1) / g;
        const int s4  = blockIdx.x * per;
        const int e4  = min(s4 + per, E4);
        const int4* __restrict__ sp = reinterpret_cast<const int4*>(src);
        for (int i = s4 + tid; i < e4; i += 256) {
            int4 s = sp[i];
            if ((unsigned)s.x < (unsigned)n) dsm[s.x] = 1;
            if ((unsigned)s.y < (unsigned)n) dsm[s.y] = 1;
            if ((unsigned)s.z < (unsigned)n) dsm[s.z] = 1;
            if ((unsigned)s.w < (unsigned)n) dsm[s.w] = 1;
        }
        if (blockIdx.x == g - 1) {
            for (int i = (E4 << 2) + tid; i < E; i += 256) {
                int s = src[i];
                if ((unsigned)s < (unsigned)n) dsm[s] = 1;
            }
        }
    }
    __syncthreads();

    // bit-pack + merge
    {
        const int nWords = (n + 31) >> 5;
        const uint4* mv = reinterpret_cast<const uint4*>(dsm);
        for (int w = tid; w < nWords; w += 256) {
            uint4 a = mv[2 * w + 0];
            uint4 c = mv[2 * w + 1];
            unsigned bits =  nibb(a.x)        | (nibb(a.y) << 4)
                          | (nibb(a.z) << 8)  | (nibb(a.w) << 12)
                          | (nibb(c.x) << 16) | (nibb(c.y) << 20)
                          | (nibb(c.z) << 24) | (nibb(c.w) << 28);
            if (bits) atomicOr(&g_bits[w], bits);
        }
    }
}

// ---------------------------------------------------------------------------
// K2: mma.sync GEMM. Tile = 64 rows x 32 cols, 128 threads.
// Warp w owns m16 block w: rows w*16..w*16+15 (cp.async + convert + mainloop
// + epilogue all warp-private). All 4 n-blocks per warp.
// A smem: [row][h1 256B | h2 256B], pitch 512B, XOR-(row&7)<<4 swizzle on
// the full byte offset. One early __syncthreads only (bias+mask publish).
// ---------------------------------------------------------------------------
__global__ __launch_bounds__(128) void gemm_mma_kernel(
    const float* __restrict__ h_in,   // [n, 128]
    const float* __restrict__ b,      // [32]
    float* __restrict__ out,          // [n, 32]
    int n)
{
    __shared__ __align__(16) unsigned char As[64 * 512];   // 32KB
    __shared__ float bs[32];
    __shared__ unsigned mb[2];

    const int tid  = threadIdx.x;
    const int w    = tid >> 5;
    const int lane = tid & 31;
    const int tile = blockIdx.x;
    const uint32_t As_b = smem_u32(As);

    // ---- phase 1: cp.async raw fp32 rows -> swizzled smem (own 16 rows) ----
    {
        #pragma unroll
        for (int it = 0; it < 16; ++it) {
            int row = w * 16 + it;
            int gr  = tile * 64 + row;
            if (gr >= n) gr = n - 1;       // clamp; stores guarded later
            const char* srcp = reinterpret_cast<const char*>(h_in) +
                               (size_t)gr * 512 + (size_t)(lane * 16);
            uint32_t dst = As_b +
                ((((uint32_t)(row * 512)) + (uint32_t)(lane * 16)) ^
                 ((uint32_t)((row & 7) << 4)));
            asm volatile("cp.async.cg.shared.global [%0], [%1], 16;"
                         :: "r"(dst), "l"(srcp) : "memory");
        }
        asm volatile("cp.async.commit_group;" ::: "memory");
    }

    // publish bias + mask words; barrier does NOT wait on the async copies
    if (tid < 32) bs[tid] = b[tid];
    if (tid < 2) {
        int wi = tile * 2 + tid;
        mb[tid] = g_bits[wi];
        g_bits[wi] = 0;                    // self-clean for next graph replay
    }
    __syncthreads();

    // ---- phase 2: wait own copies, in-place convert own rows ----
    asm volatile("cp.async.wait_group 0;" ::: "memory");
    {
        #pragma unroll 4
        for (int it = 0; it < 16; ++it) {
            int row = w * 16 + it;
            uint32_t sw = (uint32_t)((row & 7) << 4);
            uint32_t ro = (uint32_t)(row * 512);
            float4 f4;
            asm volatile("ld.shared.v4.f32 {%0,%1,%2,%3}, [%4];"
                         : "=f"(f4.x), "=f"(f4.y), "=f"(f4.z), "=f"(f4.w)
                         : "r"(As_b + ((ro + (uint32_t)(lane * 16)) ^ sw)));
            unsigned p1a = cvt2bf(f4.x, f4.y);
            unsigned p1b = cvt2bf(f4.z, f4.w);
            unsigned p2a = cvt2bf(f4.x - bf_lo(p1a), f4.y - bf_hi(p1a));
            unsigned p2b = cvt2bf(f4.z - bf_lo(p1b), f4.w - bf_hi(p1b));
            unsigned long long v1 =
                (unsigned long long)p1a | ((unsigned long long)p1b << 32);
            unsigned long long v2 =
                (unsigned long long)p2a | ((unsigned long long)p2b << 32);
            asm volatile("st.shared.b64 [%0], %1;"
                         :: "r"(As_b + ((ro + (uint32_t)(lane * 8)) ^ sw)), "l"(v1)
                         : "memory");
            asm volatile("st.shared.b64 [%0], %1;"
                         :: "r"(As_b + ((ro + 256u + (uint32_t)(lane * 8)) ^ sw)), "l"(v2)
                         : "memory");
        }
    }
    __syncwarp();   // converted rows visible to ldmatrix within the warp

    // ---- mainloop: warp-private, 8 k-iters, 4 n-blocks, 3 split phases ----
    float acc[4][4] = {};                  // [nblk][frag]

    const uint32_t colh = (uint32_t)((lane >> 4) << 4);
    const uint32_t sw   = (uint32_t)((lane & 7) << 4);
    const int rowl = w * 16 + (lane & 15);
    const uint32_t aoff = (uint32_t)(rowl * 512) + colh;
    const uint4* __restrict__ Bp = g_B4 + lane;

    #pragma unroll
    for (int t = 0; t < 8; ++t) {
        unsigned a1[4], a2[4];
        ldsm4(a1, As_b + ((aoff + (uint32_t)(t * 32)) ^ sw));         // h1
        ldsm4(a2, As_b + ((aoff + (uint32_t)(256 + t * 32)) ^ sw));   // h2
        uint4 b10 = Bp[(t * 2 + 0) * 32];        // w1, nb {0,1}
        uint4 b11 = Bp[(t * 2 + 1) * 32];        // w1, nb {2,3}
        uint4 b20 = Bp[(16 + t * 2 + 0) * 32];   // w2, nb {0,1}
        uint4 b21 = Bp[(16 + t * 2 + 1) * 32];   // w2, nb {2,3}
        mma_bf16(acc[0], a1, b10.x, b10.y);      // h1*w1
        mma_bf16(acc[1], a1, b10.z, b10.w);
        mma_bf16(acc[2], a1, b11.x, b11.y);
        mma_bf16(acc[3], a1, b11.z, b11.w);
        mma_bf16(acc[0], a2, b10.x, b10.y);      // h2*w1
        mma_bf16(acc[1], a2, b10.z, b10.w);
        mma_bf16(acc[2], a2, b11.x, b11.y);
        mma_bf16(acc[3], a2, b11.z, b11.w);
        mma_bf16(acc[0], a1, b20.x, b20.y);      // h1*w2
        mma_bf16(acc[1], a1, b20.z, b20.w);
        mma_bf16(acc[2], a1, b21.x, b21.y);
        mma_bf16(acc[3], a1, b21.z, b21.w);
    }

    // ---- epilogue: bias + mask + STG.64 (rows w*16 + lane>>2, +8) ----
    {
        const unsigned word = mb[w >> 1];          // warp-uniform mask word
        const int rt0 = w * 16 + (lane >> 2);      // in-tile row
        const int r0  = tile * 64 + rt0;
        const int r1  = r0 + 8;
        const float m0 = ((word >> (rt0 & 31)) & 1u) ? 1.0f : 0.0f;
        const float m1 = ((word >> ((rt0 + 8) & 31)) & 1u) ? 1.0f : 0.0f;
        #pragma unroll
        for (int nb = 0; nb < 4; ++nb) {
            const int c = nb * 8 + (lane & 3) * 2;
            if (r0 < n) {
                float2 v = make_float2((acc[nb][0] + bs[c]) * m0,
                                       (acc[nb][1] + bs[c + 1]) * m0);
                *reinterpret_cast<float2*>(out + (size_t)r0 * 32 + c) = v;
            }
            if (r1 < n) {
                float2 v = make_float2((acc[nb][2] + bs[c]) * m1,
                                       (acc[nb][3] + bs[c + 1]) * m1);
                *reinterpret_cast<float2*>(out + (size_t)r1 * 32 + c) = v;
            }
        }
    }
}

// ---------------------------------------------------------------------------
// Generic fallbacks (any dims) — correctness insurance only.
// ---------------------------------------------------------------------------
__global__ void generic_scatter_kernel(const int* __restrict__ src, int E) {
    int i = blockIdx.x * blockDim.x + threadIdx.x;
    int stride = gridDim.x * blockDim.x;
    for (int e = i; e < E; e += stride) g_mask[src[e]] = 1;
}
__global__ void generic_gemm_kernel(
    const float* __restrict__ h_in, const float* __restrict__ W,
    const float* __restrict__ b, float* __restrict__ out,
    int n, int f_in, int hf)
{
    long long idx = (long long)blockIdx.x * blockDim.x + threadIdx.x;
    if (idx >= (long long)n * hf) return;
    int node = (int)(idx / hf);
    int j    = (int)(idx % hf);
    const float* hr = h_in + (size_t)node * f_in;
    const float* wr = W + (size_t)j * f_in;
    float acc = b[j];
    for (int k = 0; k < f_in; ++k) acc += hr[k] * wr[k];
    out[idx] = acc;
}
__global__ void generic_maskfix_kernel(float* __restrict__ out, int n, int hf) {
    int i = blockIdx.x * blockDim.x + threadIdx.x;
    if (i >= n) return;
    unsigned char m = g_mask[i];
    g_mask[i] = 0;
    if (!m) {
        float* o = out + (size_t)i * hf;
        for (int j = 0; j < hf; ++j) o[j] = 0.0f;
    }
}

extern "C" void kernel_launch(void* const* d_in, const int* in_sizes, int n_in,
                              void* d_out, int out_size) {
    const float* h_in = (const float*)d_in[0];
    const float* W    = (const float*)d_in[1];
    const float* b    = (const float*)d_in[2];
    // d_in[3]=a_src, d_in[4]=a_tgt: provably unused after reduction
    const int* edge_index = (const int*)d_in[5];

    int HF   = in_sizes[2];               // H * F_OUT
    int F_IN = in_sizes[1] / HF;
    int n    = in_sizes[0] / F_IN;
    int E    = in_sizes[5] / 2;
    const int* src = edge_index;          // row 0 of [2, E]

    float* out = (float*)d_out;

    if (F_IN == 128 && HF == 32 && n <= 102400) {
        int mapBytes = (n + 127) & ~127;

        static int inited = 0;
        if (!inited) {
            cudaFuncSetAttribute(scatter_prep_kernel,
                                 cudaFuncAttributeMaxDynamicSharedMemorySize, 104000);
            inited = 1;
        }

        scatter_prep_kernel<<<148, 256, mapBytes>>>(src, E, n, mapBytes, W);
        int tiles = (n + 63) / 64;
        gemm_mma_kernel<<<tiles, 128>>>(h_in, b, out, n);
    } else {
        generic_scatter_kernel<<<1024, 256>>>(src, E);
        long long total = (long long)n * HF;
        generic_gemm_kernel<<<(int)((total + 255) / 256), 256>>>(
            h_in, W, b, out, n, F_IN, HF);
        generic_maskfix_kernel<<<(n + 255) / 256, 256>>>(out, n, HF);
    }
    (void)n_in; (void)out_size;
}